// round 10
// baseline (speedup 1.0000x reference)
#include <cuda_runtime.h>
#include <cstdint>

// InferenceEmbeddingTable: hash-bucket lookup + embedding row gather.
// R8 = R7 body (lane-specialized speculative slot prediction, unconditional
// speculative stores, correct cold fallback) wrapped in a PERSISTENT
// grid-stride loop: exactly one resident wave (1216 CTAs x 256 thr), each
// warp streams ~14 work-chunks back-to-back so loads-in-flight never drain
// at wave boundaries.

#define BUCKET_CAP 128
#define IPW 4                      // indices per warp-chunk

__global__ __launch_bounds__(256)
void emb_lookup_kernel(const int* __restrict__ indices,
                       const int* __restrict__ offsets,
                       const int* __restrict__ bucket_keys,    // [total_buckets*128]
                       const int* __restrict__ table_offsets,
                       const int* __restrict__ table_bucket_offsets,
                       const int* __restrict__ num_buckets,
                       const float4* __restrict__ emb,         // [total_rows*32]
                       float4* __restrict__ out,               // [N*32]
                       int N, int num_features)
{
    const int lane        = threadIdx.x & 31;
    const int warp_local  = threadIdx.x >> 5;
    const int warps_total = (gridDim.x * blockDim.x) >> 5;
    const int warp0       = blockIdx.x * (blockDim.x >> 5) + warp_local;
    const int nchunks     = (N + IPW - 1) / IPW;

    for (int chunk = warp0; chunk < nchunks; chunk += warps_total) {
        const int base = chunk * IPW;

        // ---- lanes 0..3: per-index metadata as scalars ---------------------
        int key = 0, row = 0, bg = 0, tj = 0, bl = 0, chk = (int)0x80000000;
        bool valid = false;
        if (lane < IPW) {
            const int pos = base + lane;
            key = (pos < N) ? __ldg(&indices[pos]) : 0;
            int t = 0;
            for (int f = 1; f < num_features; ++f)
                t += (pos >= __ldg(&offsets[f]));
            tj = t;
            const unsigned nb = (unsigned)__ldg(&num_buckets[t]);
            unsigned b, g;
            if ((nb & (nb - 1u)) == 0u) {             // pow2 fast path
                b = (unsigned)key & (nb - 1u);
                g = (unsigned)key >> __popc(nb - 1u);
            } else {
                b = (unsigned)key % nb;
                g = (unsigned)key / nb;
            }
            bl    = (int)b;
            valid = (g < BUCKET_CAP);
            const int gs = valid ? (int)g : 0;
            bg    = __ldg(&table_bucket_offsets[t]) + (int)b;
            row   = __ldg(&table_offsets[t]) + (int)b * BUCKET_CAP + gs;
            chk   = __ldg(&bucket_keys[bg * BUCKET_CAP + gs]);   // verify (L2)
        }

        // ---- broadcast rows, launch 4 speculative gathers (DRAM, MLP=4) ---
        const int r0 = __shfl_sync(0xffffffffu, row, 0);
        const int r1 = __shfl_sync(0xffffffffu, row, 1);
        const int r2 = __shfl_sync(0xffffffffu, row, 2);
        const int r3 = __shfl_sync(0xffffffffu, row, 3);
        const float4 v0 = __ldcs(&emb[r0 * 32 + lane]);
        const float4 v1 = __ldcs(&emb[r1 * 32 + lane]);
        const float4 v2 = __ldcs(&emb[r2 * 32 + lane]);
        const float4 v3 = __ldcs(&emb[r3 * 32 + lane]);

        // ---- unconditional speculative stores ------------------------------
        if (base + 0 < N) __stcs(&out[(base + 0) * 32 + lane], v0);
        if (base + 1 < N) __stcs(&out[(base + 1) * 32 + lane], v1);
        if (base + 2 < N) __stcs(&out[(base + 2) * 32 + lane], v2);
        if (base + 3 < N) __stcs(&out[(base + 3) * 32 + lane], v3);

        // ---- verification ballot; cold fallback overwrites bad rows --------
        const unsigned okm = __ballot_sync(0xffffffffu,
                                           (lane < IPW) && valid && (chk == key));
        if (__builtin_expect((okm & 0xfu) != 0xfu, 0)) {
            #pragma unroll
            for (int j = 0; j < IPW; ++j) {
                const int pos = base + j;
                if (pos >= N) break;
                if ((okm >> j) & 1u) continue;
                const int kj  = __shfl_sync(0xffffffffu, key, j);
                const int bgj = __shfl_sync(0xffffffffu, bg,  j);
                const int tjj = __shfl_sync(0xffffffffu, tj,  j);
                const int blj = __shfl_sync(0xffffffffu, bl,  j);
                const int4 kk = __ldg((const int4*)bucket_keys + bgj * 32 + lane);
                const int m = (kk.x == kj ? 1 : 0) | (kk.y == kj ? 2 : 0)
                            | (kk.z == kj ? 4 : 0) | (kk.w == kj ? 8 : 0);
                const int cand = m ? (lane * 4 + (__ffs(m) - 1)) : 0x7fffffff;
                const int slot = __reduce_min_sync(0xffffffffu, cand);
                float4 rr = make_float4(0.f, 0.f, 0.f, 0.f);
                if (slot < BUCKET_CAP) {
                    const int row2 = __ldg(&table_offsets[tjj])
                                   + blj * BUCKET_CAP + slot;
                    rr = __ldcs(&emb[row2 * 32 + lane]);
                }
                __stcs(&out[pos * 32 + lane], rr);   // overwrites speculation
            }
        }
    }
}

extern "C" void kernel_launch(void* const* d_in, const int* in_sizes, int n_in,
                              void* d_out, int out_size)
{
    const int*    indices              = (const int*)   d_in[0];
    const int*    offsets              = (const int*)   d_in[1];
    const int*    bucket_keys          = (const int*)   d_in[2];
    const int*    table_offsets        = (const int*)   d_in[3];
    const int*    table_bucket_offsets = (const int*)   d_in[4];
    const int*    num_buckets          = (const int*)   d_in[5];
    const float4* emb                  = (const float4*)d_in[6];
    float4*       out                  = (float4*)      d_out;

    const int N            = in_sizes[0];
    const int num_features = in_sizes[5];

    const int threads = 256;                 // 8 warps/block, 32 idx per pass
    // One full resident wave: 152 SMs x 8 blocks (256 thr, 32 regs -> 2048
    // thr/SM). Cap by actual need.
    const int idx_per_block = (threads / 32) * IPW;
    const int need = (N + idx_per_block - 1) / idx_per_block;
    const int blocks = (need < 1216) ? need : 1216;

    emb_lookup_kernel<<<blocks, threads>>>(indices, offsets, bucket_keys,
                                           table_offsets, table_bucket_offsets,
                                           num_buckets, emb, out,
                                           N, num_features);
}

// round 11
// speedup vs baseline: 1.1261x; 1.1261x over previous
#include <cuda_runtime.h>
#include <cstdint>

// InferenceEmbeddingTable: hash-bucket lookup + embedding row gather.
// R9 = R7 (best: IPW=4, 256 thr, lane-specialized speculative slot predict,
// unconditional speculative stores, correct cold fallback) with ONE change:
// emb gathers use default caching (__ldg) instead of __ldcs, allowing ~12%
// L2 hits on the random 1GB gather (L2 = 126MB); output stores stay __stcs
// (evict-first) so the 256MB write stream doesn't pollute L2.

#define BUCKET_CAP 128
#define IPW 4                      // indices per warp

__global__ __launch_bounds__(256)
void emb_lookup_kernel(const int* __restrict__ indices,
                       const int* __restrict__ offsets,
                       const int* __restrict__ bucket_keys,    // [total_buckets*128]
                       const int* __restrict__ table_offsets,
                       const int* __restrict__ table_bucket_offsets,
                       const int* __restrict__ num_buckets,
                       const float4* __restrict__ emb,         // [total_rows*32]
                       float4* __restrict__ out,               // [N*32]
                       int N, int num_features)
{
    const int gtid = blockIdx.x * blockDim.x + threadIdx.x;
    const int warp = gtid >> 5;
    const int lane = threadIdx.x & 31;
    const int base = warp * IPW;
    if (base >= N) return;

    // ---- lanes 0..3: per-index metadata as scalars -------------------------
    int key = 0, row = 0, bg = 0, tj = 0, bl = 0, chk = (int)0x80000000;
    bool valid = false;
    if (lane < IPW) {
        const int pos = base + lane;
        key = (pos < N) ? __ldg(&indices[pos]) : 0;
        int t = 0;
        for (int f = 1; f < num_features; ++f)
            t += (pos >= __ldg(&offsets[f]));
        tj = t;
        const unsigned nb = (unsigned)__ldg(&num_buckets[t]);
        unsigned b, g;
        if ((nb & (nb - 1u)) == 0u) {                 // pow2 fast path
            b = (unsigned)key & (nb - 1u);
            g = (unsigned)key >> __popc(nb - 1u);
        } else {
            b = (unsigned)key % nb;
            g = (unsigned)key / nb;
        }
        bl    = (int)b;
        valid = (g < BUCKET_CAP);
        const int gs = valid ? (int)g : 0;
        bg    = __ldg(&table_bucket_offsets[t]) + (int)b;
        row   = __ldg(&table_offsets[t]) + (int)b * BUCKET_CAP + gs;
        chk   = __ldg(&bucket_keys[bg * BUCKET_CAP + gs]);   // verify (L2)
    }

    // ---- broadcast rows, launch 4 speculative gathers (DRAM, MLP=4) -------
    const int r0 = __shfl_sync(0xffffffffu, row, 0);
    const int r1 = __shfl_sync(0xffffffffu, row, 1);
    const int r2 = __shfl_sync(0xffffffffu, row, 2);
    const int r3 = __shfl_sync(0xffffffffu, row, 3);
    const float4 v0 = __ldg(&emb[r0 * 32 + lane]);   // default policy: keep in L2
    const float4 v1 = __ldg(&emb[r1 * 32 + lane]);
    const float4 v2 = __ldg(&emb[r2 * 32 + lane]);
    const float4 v3 = __ldg(&emb[r3 * 32 + lane]);

    // ---- unconditional speculative stores (no ballot on the store path) ---
    if (base + 0 < N) __stcs(&out[(base + 0) * 32 + lane], v0);
    if (base + 1 < N) __stcs(&out[(base + 1) * 32 + lane], v1);
    if (base + 2 < N) __stcs(&out[(base + 2) * 32 + lane], v2);
    if (base + 3 < N) __stcs(&out[(base + 3) * 32 + lane], v3);

    // ---- verification ballot; cold fallback overwrites bad rows -----------
    const unsigned okm = __ballot_sync(0xffffffffu,
                                       (lane < IPW) && valid && (chk == key));
    if (__builtin_expect((okm & 0xfu) != 0xfu, 0)) {
        #pragma unroll
        for (int j = 0; j < IPW; ++j) {
            const int pos = base + j;
            if (pos >= N) break;
            if ((okm >> j) & 1u) continue;
            const int kj  = __shfl_sync(0xffffffffu, key, j);
            const int bgj = __shfl_sync(0xffffffffu, bg,  j);
            const int tjj = __shfl_sync(0xffffffffu, tj,  j);
            const int blj = __shfl_sync(0xffffffffu, bl,  j);
            const int4 kk = __ldg((const int4*)bucket_keys + bgj * 32 + lane);
            const int m = (kk.x == kj ? 1 : 0) | (kk.y == kj ? 2 : 0)
                        | (kk.z == kj ? 4 : 0) | (kk.w == kj ? 8 : 0);
            const int cand = m ? (lane * 4 + (__ffs(m) - 1)) : 0x7fffffff;
            const int slot = __reduce_min_sync(0xffffffffu, cand);
            float4 rr = make_float4(0.f, 0.f, 0.f, 0.f);
            if (slot < BUCKET_CAP) {
                const int row2 = __ldg(&table_offsets[tjj]) + blj * BUCKET_CAP + slot;
                rr = __ldg(&emb[row2 * 32 + lane]);
            }
            __stcs(&out[pos * 32 + lane], rr);   // later in program order:
        }                                        // overwrites the speculation
    }
}

extern "C" void kernel_launch(void* const* d_in, const int* in_sizes, int n_in,
                              void* d_out, int out_size)
{
    const int*    indices              = (const int*)   d_in[0];
    const int*    offsets              = (const int*)   d_in[1];
    const int*    bucket_keys          = (const int*)   d_in[2];
    const int*    table_offsets        = (const int*)   d_in[3];
    const int*    table_bucket_offsets = (const int*)   d_in[4];
    const int*    num_buckets          = (const int*)   d_in[5];
    const float4* emb                  = (const float4*)d_in[6];
    float4*       out                  = (float4*)      d_out;

    const int N            = in_sizes[0];
    const int num_features = in_sizes[5];

    const int threads = 256;                       // 8 warps * 4 idx = 32 idx/block
    const int idx_per_block = (threads / 32) * IPW;
    const int blocks = (N + idx_per_block - 1) / idx_per_block;

    emb_lookup_kernel<<<blocks, threads>>>(indices, offsets, bucket_keys,
                                           table_offsets, table_bucket_offsets,
                                           num_buckets, emb, out,
                                           N, num_features);
}

// round 13
// speedup vs baseline: 1.1270x; 1.0008x over previous
#include <cuda_runtime.h>
#include <cstdint>

// InferenceEmbeddingTable: hash-bucket lookup + embedding row gather.
// R10 = R9 (IPW=4, 256 thr, lane-specialized speculative slot prediction,
// unconditional speculative stores, correct cold fallback, default-L2 gather,
// __stcs output) with ONE change: emb gathers use __ldlu (last-use) so the
// zero-L1-reuse 512B rows bypass L1 allocation (keeping L2 policy intact),
// leaving L1 to the per-warp metadata that lanes 0..3 re-read.

#define BUCKET_CAP 128
#define IPW 4                      // indices per warp

__global__ __launch_bounds__(256)
void emb_lookup_kernel(const int* __restrict__ indices,
                       const int* __restrict__ offsets,
                       const int* __restrict__ bucket_keys,    // [total_buckets*128]
                       const int* __restrict__ table_offsets,
                       const int* __restrict__ table_bucket_offsets,
                       const int* __restrict__ num_buckets,
                       const float4* __restrict__ emb,         // [total_rows*32]
                       float4* __restrict__ out,               // [N*32]
                       int N, int num_features)
{
    const int gtid = blockIdx.x * blockDim.x + threadIdx.x;
    const int warp = gtid >> 5;
    const int lane = threadIdx.x & 31;
    const int base = warp * IPW;
    if (base >= N) return;

    // ---- lanes 0..3: per-index metadata as scalars -------------------------
    int key = 0, row = 0, bg = 0, tj = 0, bl = 0, chk = (int)0x80000000;
    bool valid = false;
    if (lane < IPW) {
        const int pos = base + lane;
        key = (pos < N) ? __ldg(&indices[pos]) : 0;
        int t = 0;
        for (int f = 1; f < num_features; ++f)
            t += (pos >= __ldg(&offsets[f]));
        tj = t;
        const unsigned nb = (unsigned)__ldg(&num_buckets[t]);
        unsigned b, g;
        if ((nb & (nb - 1u)) == 0u) {                 // pow2 fast path
            b = (unsigned)key & (nb - 1u);
            g = (unsigned)key >> __popc(nb - 1u);
        } else {
            b = (unsigned)key % nb;
            g = (unsigned)key / nb;
        }
        bl    = (int)b;
        valid = (g < BUCKET_CAP);
        const int gs = valid ? (int)g : 0;
        bg    = __ldg(&table_bucket_offsets[t]) + (int)b;
        row   = __ldg(&table_offsets[t]) + (int)b * BUCKET_CAP + gs;
        chk   = __ldg(&bucket_keys[bg * BUCKET_CAP + gs]);   // verify (L2)
    }

    // ---- broadcast rows, launch 4 speculative gathers (DRAM, MLP=4) -------
    // __ldlu: last-use -> no L1 allocation (no reuse), default L2 policy.
    const int r0 = __shfl_sync(0xffffffffu, row, 0);
    const int r1 = __shfl_sync(0xffffffffu, row, 1);
    const int r2 = __shfl_sync(0xffffffffu, row, 2);
    const int r3 = __shfl_sync(0xffffffffu, row, 3);
    const float4 v0 = __ldlu(&emb[r0 * 32 + lane]);
    const float4 v1 = __ldlu(&emb[r1 * 32 + lane]);
    const float4 v2 = __ldlu(&emb[r2 * 32 + lane]);
    const float4 v3 = __ldlu(&emb[r3 * 32 + lane]);

    // ---- unconditional speculative stores (no ballot on the store path) ---
    if (base + 0 < N) __stcs(&out[(base + 0) * 32 + lane], v0);
    if (base + 1 < N) __stcs(&out[(base + 1) * 32 + lane], v1);
    if (base + 2 < N) __stcs(&out[(base + 2) * 32 + lane], v2);
    if (base + 3 < N) __stcs(&out[(base + 3) * 32 + lane], v3);

    // ---- verification ballot; cold fallback overwrites bad rows -----------
    const unsigned okm = __ballot_sync(0xffffffffu,
                                       (lane < IPW) && valid && (chk == key));
    if (__builtin_expect((okm & 0xfu) != 0xfu, 0)) {
        #pragma unroll
        for (int j = 0; j < IPW; ++j) {
            const int pos = base + j;
            if (pos >= N) break;
            if ((okm >> j) & 1u) continue;
            const int kj  = __shfl_sync(0xffffffffu, key, j);
            const int bgj = __shfl_sync(0xffffffffu, bg,  j);
            const int tjj = __shfl_sync(0xffffffffu, tj,  j);
            const int blj = __shfl_sync(0xffffffffu, bl,  j);
            const int4 kk = __ldg((const int4*)bucket_keys + bgj * 32 + lane);
            const int m = (kk.x == kj ? 1 : 0) | (kk.y == kj ? 2 : 0)
                        | (kk.z == kj ? 4 : 0) | (kk.w == kj ? 8 : 0);
            const int cand = m ? (lane * 4 + (__ffs(m) - 1)) : 0x7fffffff;
            const int slot = __reduce_min_sync(0xffffffffu, cand);
            float4 rr = make_float4(0.f, 0.f, 0.f, 0.f);
            if (slot < BUCKET_CAP) {
                const int row2 = __ldg(&table_offsets[tjj]) + blj * BUCKET_CAP + slot;
                rr = __ldg(&emb[row2 * 32 + lane]);
            }
            __stcs(&out[pos * 32 + lane], rr);   // later in program order:
        }                                        // overwrites the speculation
    }
}

extern "C" void kernel_launch(void* const* d_in, const int* in_sizes, int n_in,
                              void* d_out, int out_size)
{
    const int*    indices              = (const int*)   d_in[0];
    const int*    offsets              = (const int*)   d_in[1];
    const int*    bucket_keys          = (const int*)   d_in[2];
    const int*    table_offsets        = (const int*)   d_in[3];
    const int*    table_bucket_offsets = (const int*)   d_in[4];
    const int*    num_buckets          = (const int*)   d_in[5];
    const float4* emb                  = (const float4*)d_in[6];
    float4*       out                  = (float4*)      d_out;

    const int N            = in_sizes[0];
    const int num_features = in_sizes[5];

    const int threads = 256;                       // 8 warps * 4 idx = 32 idx/block
    const int idx_per_block = (threads / 32) * IPW;
    const int blocks = (N + idx_per_block - 1) / idx_per_block;

    emb_lookup_kernel<<<blocks, threads>>>(indices, offsets, bucket_keys,
                                           table_offsets, table_bucket_offsets,
                                           num_buckets, emb, out,
                                           N, num_features);
}